// round 2
// baseline (speedup 1.0000x reference)
#include <cuda_runtime.h>
#include <mma.h>
#include <math.h>

using namespace nvcuda;

#define BATCH  64
#define SEQ    512
#define INSZ   1024
#define HID    1024
#define G4     4096
#define BSH    (BATCH * SEQ * HID)

// Scratch (device globals: allocation-free per harness rules)
__device__ float g_Gx[(size_t)SEQ * BATCH * G4];   // [t][b][4096] = 512 MB
__device__ float g_C[BATCH * HID];
__device__ float g_hbuf[2][BATCH * HID];           // ping-pong running-max (next-step input)

__global__ void k_zeroC() {
    int i = blockIdx.x * blockDim.x + threadIdx.x;
    if (i < BATCH * HID) g_C[i] = 0.f;
}

// ---------------------------------------------------------------------------
// Phase 1: Gx[t*64 + b][gate*1024 + c] = sum_k x[b,t,k] * Wgate[1024+k][c]
// (bias added later in the step kernel). tf32 wmma, 128x128 tile, BK=32.
// ---------------------------------------------------------------------------
__global__ __launch_bounds__(256) void k_gemm_x(
    const float* __restrict__ x,
    const float* __restrict__ Wf, const float* __restrict__ Wi,
    const float* __restrict__ Wc, const float* __restrict__ Wo)
{
    __shared__ float sA[128][40];    // 128 rows x 32 k (pad->40: 160B rows, 32B aligned)
    __shared__ float sB[32][136];    // 32 k x 128 cols (pad->136: 544B rows)

    const int bn = blockIdx.x;            // 0..31  (N tiles of 128 over 4096)
    const int bm = blockIdx.y;            // 0..255 (M tiles of 128 over 32768)
    const int gate = bn >> 3;
    const int c0 = (bn & 7) * 128;
    const float* W = (gate == 0) ? Wf : (gate == 1) ? Wi : (gate == 2) ? Wc : Wo;

    const int tid  = threadIdx.x;
    const int warp = tid >> 5;            // 8 warps: 4 (m) x 2 (n)
    const int wm   = warp & 3;            // m offset wm*32
    const int wn   = warp >> 2;           // n offset wn*64

    wmma::fragment<wmma::accumulator, 16, 16, 8, float> acc[2][4];
#pragma unroll
    for (int i = 0; i < 2; i++)
#pragma unroll
        for (int j = 0; j < 4; j++) wmma::fill_fragment(acc[i][j], 0.f);

    for (int kc = 0; kc < 32; ++kc) {
        // Load A tile: 128x32 from x
#pragma unroll
        for (int l = 0; l < 4; l++) {
            int f = tid + l * 256;                 // 0..1023 float4s
            int r = f >> 3, c4 = f & 7;
            float4 v = *reinterpret_cast<const float4*>(
                x + (size_t)(bm * 128 + r) * 1024 + kc * 32 + c4 * 4);
            sA[r][c4 * 4 + 0] = v.x; sA[r][c4 * 4 + 1] = v.y;
            sA[r][c4 * 4 + 2] = v.z; sA[r][c4 * 4 + 3] = v.w;
        }
        // Load B tile: 32x128 from W's x-part (rows 1024..2047)
#pragma unroll
        for (int l = 0; l < 4; l++) {
            int f = tid + l * 256;
            int kr = f >> 5, c4 = f & 31;
            float4 v = *reinterpret_cast<const float4*>(
                W + (size_t)(1024 + kc * 32 + kr) * 1024 + c0 + c4 * 4);
            sB[kr][c4 * 4 + 0] = v.x; sB[kr][c4 * 4 + 1] = v.y;
            sB[kr][c4 * 4 + 2] = v.z; sB[kr][c4 * 4 + 3] = v.w;
        }
        __syncthreads();

#pragma unroll
        for (int kk = 0; kk < 4; ++kk) {
            wmma::fragment<wmma::matrix_a, 16, 16, 8, wmma::precision::tf32, wmma::row_major> af[2];
            wmma::fragment<wmma::matrix_b, 16, 16, 8, wmma::precision::tf32, wmma::row_major> bfr[4];
#pragma unroll
            for (int i = 0; i < 2; i++) {
                wmma::load_matrix_sync(af[i], &sA[wm * 32 + i * 16][kk * 8], 40);
#pragma unroll
                for (int e = 0; e < af[i].num_elements; e++)
                    af[i].x[e] = wmma::__float_to_tf32(af[i].x[e]);
            }
#pragma unroll
            for (int j = 0; j < 4; j++) {
                wmma::load_matrix_sync(bfr[j], &sB[kk * 8][wn * 64 + j * 16], 136);
#pragma unroll
                for (int e = 0; e < bfr[j].num_elements; e++)
                    bfr[j].x[e] = wmma::__float_to_tf32(bfr[j].x[e]);
            }
#pragma unroll
            for (int i = 0; i < 2; i++)
#pragma unroll
                for (int j = 0; j < 4; j++)
                    wmma::mma_sync(acc[i][j], af[i], bfr[j], acc[i][j]);
        }
        __syncthreads();
    }

    // Store with the row remap m = b*512 + t  ->  out row = t*64 + b.
    // Within a 16-row fragment t advances by 1 (b fixed), so the scatter is a
    // constant row stride of 64*4096 -> fold it into ldm.
#pragma unroll
    for (int i = 0; i < 2; i++) {
        int m0 = bm * 128 + wm * 32 + i * 16;
        int bidx = m0 >> 9;
        int t0 = m0 & 511;
        float* rowbase = g_Gx + (size_t)(t0 * 64 + bidx) * G4 + gate * 1024 + c0 + wn * 64;
#pragma unroll
        for (int j = 0; j < 4; j++)
            wmma::store_matrix_sync(rowbase + j * 16, acc[i][j],
                                    (unsigned)(64 * G4), wmma::mem_row_major);
    }
}

// ---------------------------------------------------------------------------
// Phase 2: one launch per timestep. grid (64 hidden-tiles of 16, 2 row-halves
// of 32). Each CTA: g_rec = h_in(32x1024) @ Wh(1024 x 4*16), fused gates +
// state update + cummax + outputs.
// ---------------------------------------------------------------------------
__global__ __launch_bounds__(128) void k_step(
    const float* __restrict__ Wf, const float* __restrict__ Wi,
    const float* __restrict__ Wc, const float* __restrict__ Wo,
    const float* __restrict__ bfv, const float* __restrict__ biv,
    const float* __restrict__ bcv, const float* __restrict__ bov,
    float* __restrict__ out, int t)
{
    __shared__ float sA[32][40];        // h_in rows x k chunk
    __shared__ float sB[4][32][24];     // per-gate weight chunk (k x 16)
    __shared__ float sG[4][32][24];     // staged recurrent gate pre-activations

    const int h0 = blockIdx.x * 16;
    const int r0 = blockIdx.y * 32;
    const int tid = threadIdx.x;
    const int warp = tid >> 5;          // warp == gate

    wmma::fragment<wmma::accumulator, 16, 16, 8, float> acc[2];
    wmma::fill_fragment(acc[0], 0.f);
    wmma::fill_fragment(acc[1], 0.f);

    if (t > 0) {
        const float* __restrict__ hin = g_hbuf[(t + 1) & 1];
        for (int kc = 0; kc < 32; ++kc) {
            // A: 32x32 slab of h_in
#pragma unroll
            for (int l = 0; l < 2; l++) {
                int f = tid + l * 128;            // 0..255 float4s
                int r = f >> 3, c4 = f & 7;
                float4 v = *reinterpret_cast<const float4*>(
                    hin + (size_t)(r0 + r) * 1024 + kc * 32 + c4 * 4);
                sA[r][c4 * 4 + 0] = v.x; sA[r][c4 * 4 + 1] = v.y;
                sA[r][c4 * 4 + 2] = v.z; sA[r][c4 * 4 + 3] = v.w;
            }
            // B: per gate, 32(k) x 16(h) from W's h-part (rows 0..1023)
#pragma unroll
            for (int l = 0; l < 4; l++) {
                int f = tid + l * 128;            // 0..511 float4s
                int g = f >> 7;
                int rem = f & 127;
                int kr = rem >> 2, c4 = rem & 3;
                const float* W = (g == 0) ? Wf : (g == 1) ? Wi : (g == 2) ? Wc : Wo;
                float4 v = *reinterpret_cast<const float4*>(
                    W + (size_t)(kc * 32 + kr) * 1024 + h0 + c4 * 4);
                sB[g][kr][c4 * 4 + 0] = v.x; sB[g][kr][c4 * 4 + 1] = v.y;
                sB[g][kr][c4 * 4 + 2] = v.z; sB[g][kr][c4 * 4 + 3] = v.w;
            }
            __syncthreads();

#pragma unroll
            for (int kk = 0; kk < 4; ++kk) {
                wmma::fragment<wmma::matrix_a, 16, 16, 8, wmma::precision::tf32, wmma::row_major> a0, a1;
                wmma::fragment<wmma::matrix_b, 16, 16, 8, wmma::precision::tf32, wmma::row_major> bb;
                wmma::load_matrix_sync(a0, &sA[0][kk * 8], 40);
                wmma::load_matrix_sync(a1, &sA[16][kk * 8], 40);
                wmma::load_matrix_sync(bb, &sB[warp][kk * 8][0], 24);
#pragma unroll
                for (int e = 0; e < a0.num_elements; e++) {
                    a0.x[e] = wmma::__float_to_tf32(a0.x[e]);
                    a1.x[e] = wmma::__float_to_tf32(a1.x[e]);
                }
#pragma unroll
                for (int e = 0; e < bb.num_elements; e++)
                    bb.x[e] = wmma::__float_to_tf32(bb.x[e]);
                wmma::mma_sync(acc[0], a0, bb, acc[0]);
                wmma::mma_sync(acc[1], a1, bb, acc[1]);
            }
            __syncthreads();
        }
    }

    wmma::store_matrix_sync(&sG[warp][0][0],  acc[0], 24, wmma::mem_row_major);
    wmma::store_matrix_sync(&sG[warp][16][0], acc[1], 24, wmma::mem_row_major);
    __syncthreads();

    const float* __restrict__ hprev = g_hbuf[(t + 1) & 1];
    float* __restrict__ hnew = g_hbuf[t & 1];

#pragma unroll
    for (int l = 0; l < 4; l++) {
        int it = tid + l * 128;                 // 0..511 = 32 rows x 16 hid
        int r = it >> 4, hh = it & 15;
        int b = r0 + r, h = h0 + hh;
        size_t gbase = (size_t)(t * 64 + b) * G4;

        float gf = sG[0][r][hh] + g_Gx[gbase + h]        + bfv[h];
        float gi = sG[1][r][hh] + g_Gx[gbase + 1024 + h] + biv[h];
        float gc = sG[2][r][hh] + g_Gx[gbase + 2048 + h] + bcv[h];
        float go = sG[3][r][hh] + g_Gx[gbase + 3072 + h] + bov[h];

        float fg = 1.f / (1.f + expf(-gf));
        float ig = 1.f / (1.f + expf(-gi));
        float cg = tanhf(gc);
        float og = 1.f / (1.f + expf(-go));

        int idx = b * HID + h;
        float Cn = fg * g_C[idx] + ig * cg;
        g_C[idx] = Cn;
        float hv = og * tanhf(Cn);

        out[(size_t)b * SEQ * HID + (size_t)t * HID + h] = hv;

        float hm = (t == 0) ? hv : fmaxf(hprev[idx], hv);
        hnew[idx] = hm;

        if (t == SEQ - 1) {
            out[(size_t)BSH + idx] = hm;                 // h_fin = final running max
            out[(size_t)BSH + BATCH * HID + idx] = Cn;   // C_fin
        }
    }
}

extern "C" void kernel_launch(void* const* d_in, const int* in_sizes, int n_in,
                              void* d_out, int out_size) {
    const float* x  = (const float*)d_in[0];
    const float* Wf = (const float*)d_in[1];
    const float* bf = (const float*)d_in[2];
    const float* Wi = (const float*)d_in[3];
    const float* bi = (const float*)d_in[4];
    const float* Wc = (const float*)d_in[5];
    const float* bc = (const float*)d_in[6];
    const float* Wo = (const float*)d_in[7];
    const float* bo = (const float*)d_in[8];
    float* out = (float*)d_out;

    k_zeroC<<<64, 1024>>>();
    k_gemm_x<<<dim3(32, 256), 256>>>(x, Wf, Wi, Wc, Wo);
    for (int t = 0; t < SEQ; ++t)
        k_step<<<dim3(64, 2), 128>>>(Wf, Wi, Wc, Wo, bf, bi, bc, bo, out, t);
}

// round 3
// speedup vs baseline: 1.6138x; 1.6138x over previous
#include <cuda_runtime.h>
#include <mma.h>
#include <math.h>

using namespace nvcuda;

#define BATCH  64
#define SEQ    512
#define INSZ   1024
#define HID    1024
#define G4     4096
#define BSH    (BATCH * SEQ * HID)
#define CTAS   128
#define THREADS 256
#define HB     8           // hidden units per CTA
#define NC     32          // gate-columns per CTA (4 gates x 8)
#define SWP    34          // sW row pitch (floats)
#define SHP    132         // sH row pitch (floats)
#define SPP    34          // sP row pitch (floats)

// Scratch (device globals: allocation-free per harness rules)
__device__ float g_Gx[(size_t)SEQ * BATCH * G4];   // [t][b][4096] = 512 MB
__device__ float g_hbuf[2][BATCH * HID];           // ping-pong running-max h
__device__ unsigned g_bar[SEQ];                    // per-step barrier counters

__global__ void k_init() {
    int i = blockIdx.x * blockDim.x + threadIdx.x;
    if (i < SEQ) g_bar[i] = 0u;
}

// ---------------------------------------------------------------------------
// Phase 1: Gx[t*64 + b][gate*1024 + c] = sum_k x[b,t,k] * Wgate[1024+k][c]
// tf32 wmma, 128x128 tile, BK=32.  (unchanged from R1 — passed)
// ---------------------------------------------------------------------------
__global__ __launch_bounds__(256) void k_gemm_x(
    const float* __restrict__ x,
    const float* __restrict__ Wf, const float* __restrict__ Wi,
    const float* __restrict__ Wc, const float* __restrict__ Wo)
{
    __shared__ float sA[128][40];
    __shared__ float sB[32][136];

    const int bn = blockIdx.x;
    const int bm = blockIdx.y;
    const int gate = bn >> 3;
    const int c0 = (bn & 7) * 128;
    const float* W = (gate == 0) ? Wf : (gate == 1) ? Wi : (gate == 2) ? Wc : Wo;

    const int tid  = threadIdx.x;
    const int warp = tid >> 5;
    const int wm   = warp & 3;
    const int wn   = warp >> 2;

    wmma::fragment<wmma::accumulator, 16, 16, 8, float> acc[2][4];
#pragma unroll
    for (int i = 0; i < 2; i++)
#pragma unroll
        for (int j = 0; j < 4; j++) wmma::fill_fragment(acc[i][j], 0.f);

    for (int kc = 0; kc < 32; ++kc) {
#pragma unroll
        for (int l = 0; l < 4; l++) {
            int f = tid + l * 256;
            int r = f >> 3, c4 = f & 7;
            float4 v = *reinterpret_cast<const float4*>(
                x + (size_t)(bm * 128 + r) * 1024 + kc * 32 + c4 * 4);
            sA[r][c4 * 4 + 0] = v.x; sA[r][c4 * 4 + 1] = v.y;
            sA[r][c4 * 4 + 2] = v.z; sA[r][c4 * 4 + 3] = v.w;
        }
#pragma unroll
        for (int l = 0; l < 4; l++) {
            int f = tid + l * 256;
            int kr = f >> 5, c4 = f & 31;
            float4 v = *reinterpret_cast<const float4*>(
                W + (size_t)(1024 + kc * 32 + kr) * 1024 + c0 + c4 * 4);
            sB[kr][c4 * 4 + 0] = v.x; sB[kr][c4 * 4 + 1] = v.y;
            sB[kr][c4 * 4 + 2] = v.z; sB[kr][c4 * 4 + 3] = v.w;
        }
        __syncthreads();

#pragma unroll
        for (int kk = 0; kk < 4; ++kk) {
            wmma::fragment<wmma::matrix_a, 16, 16, 8, wmma::precision::tf32, wmma::row_major> af[2];
            wmma::fragment<wmma::matrix_b, 16, 16, 8, wmma::precision::tf32, wmma::row_major> bfr[4];
#pragma unroll
            for (int i = 0; i < 2; i++) {
                wmma::load_matrix_sync(af[i], &sA[wm * 32 + i * 16][kk * 8], 40);
#pragma unroll
                for (int e = 0; e < af[i].num_elements; e++)
                    af[i].x[e] = wmma::__float_to_tf32(af[i].x[e]);
            }
#pragma unroll
            for (int j = 0; j < 4; j++) {
                wmma::load_matrix_sync(bfr[j], &sB[kk * 8][wn * 64 + j * 16], 136);
#pragma unroll
                for (int e = 0; e < bfr[j].num_elements; e++)
                    bfr[j].x[e] = wmma::__float_to_tf32(bfr[j].x[e]);
            }
#pragma unroll
            for (int i = 0; i < 2; i++)
#pragma unroll
                for (int j = 0; j < 4; j++)
                    wmma::mma_sync(acc[i][j], af[i], bfr[j], acc[i][j]);
        }
        __syncthreads();
    }

#pragma unroll
    for (int i = 0; i < 2; i++) {
        int m0 = bm * 128 + wm * 32 + i * 16;
        int bidx = m0 >> 9;
        int t0 = m0 & 511;
        float* rowbase = g_Gx + (size_t)(t0 * 64 + bidx) * G4 + gate * 1024 + c0 + wn * 64;
#pragma unroll
        for (int j = 0; j < 4; j++)
            wmma::store_matrix_sync(rowbase + j * 16, acc[i][j],
                                    (unsigned)(64 * G4), wmma::mem_row_major);
    }
}

// ---------------------------------------------------------------------------
// Phase 2: ONE persistent kernel. 128 CTAs x 256 threads, 1 CTA/SM.
// CTA j owns hidden units [8j, 8j+8) for all 4 gates (32 weight columns),
// kept in SMEM for the whole sequence. C and running-max h kept in registers.
// Grid-wide sync via per-step counters.
// ---------------------------------------------------------------------------
__device__ __forceinline__ float sigf(float v) { return 1.f / (1.f + expf(-v)); }

__global__ __launch_bounds__(THREADS, 1) void k_lstm(
    const float* __restrict__ Wf, const float* __restrict__ Wi,
    const float* __restrict__ Wc, const float* __restrict__ Wo,
    const float* __restrict__ bfv, const float* __restrict__ biv,
    const float* __restrict__ bcv, const float* __restrict__ bov,
    float* __restrict__ out)
{
    extern __shared__ float smem[];
    float* sW    = smem;                    // [1024][SWP]  weights (resident)
    float* arena = smem + 1024 * SWP;       // sH[2][64][SHP]  /  sP[8][64][SPP]

    __shared__ float sBias[NC];

    const int tid  = threadIdx.x;
    const int warp = tid >> 5;              // 8 warps, K-split
    const int blk  = blockIdx.x;            // 0..127
    const int h0   = blk * HB;

    // ---- one-time: preload this CTA's 32 weight columns into SMEM ----
    for (int k = tid; k < 1024; k += THREADS) {
#pragma unroll
        for (int g = 0; g < 4; g++) {
            const float* W = (g == 0) ? Wf : (g == 1) ? Wi : (g == 2) ? Wc : Wo;
            float4 v0 = *reinterpret_cast<const float4*>(W + (size_t)k * 1024 + h0);
            float4 v1 = *reinterpret_cast<const float4*>(W + (size_t)k * 1024 + h0 + 4);
            float* d = &sW[k * SWP + g * 8];
            d[0] = v0.x; d[1] = v0.y; d[2] = v0.z; d[3] = v0.w;
            d[4] = v1.x; d[5] = v1.y; d[6] = v1.z; d[7] = v1.w;
        }
    }
    if (tid < NC) {
        int g = tid >> 3, hh = tid & 7;
        const float* bv = (g == 0) ? bfv : (g == 1) ? biv : (g == 2) ? bcv : bov;
        sBias[tid] = bv[h0 + hh];
    }
    __syncthreads();

    // per-thread persistent state: elems e = tid, tid+256 of (64 b x 8 hh)
    float creg[2] = {0.f, 0.f};
    float hreg[2] = {0.f, 0.f};

    for (int t = 0; t < SEQ; ++t) {
        // ---------------- recurrent GEMM: g_rec = h_in(64x1024) @ sW ----------
        if (t > 0) {
            const float* __restrict__ hin = g_hbuf[(t + 1) & 1];
            float4 pf[8];
            // prologue: chunk 0 (k = 0..127)
#pragma unroll
            for (int l = 0; l < 8; l++) {
                int idx = tid + l * THREADS;     // 0..2047 float4s
                int r = idx >> 5, c4 = idx & 31;
                pf[l] = __ldcg(reinterpret_cast<const float4*>(hin + (size_t)r * 1024 + c4 * 4));
            }
#pragma unroll
            for (int l = 0; l < 8; l++) {
                int idx = tid + l * THREADS;
                int r = idx >> 5, c4 = idx & 31;
                float* d = &arena[r * SHP + c4 * 4];
                d[0] = pf[l].x; d[1] = pf[l].y; d[2] = pf[l].z; d[3] = pf[l].w;
            }
            __syncthreads();

            wmma::fragment<wmma::accumulator, 16, 16, 8, float> acc[4][2];
#pragma unroll
            for (int i = 0; i < 4; i++) {
                wmma::fill_fragment(acc[i][0], 0.f);
                wmma::fill_fragment(acc[i][1], 0.f);
            }

            for (int c = 0; c < 8; ++c) {
                // prefetch chunk c+1 into regs (overlaps MMA below)
                if (c < 7) {
#pragma unroll
                    for (int l = 0; l < 8; l++) {
                        int idx = tid + l * THREADS;
                        int r = idx >> 5, c4 = idx & 31;
                        pf[l] = __ldcg(reinterpret_cast<const float4*>(
                            hin + (size_t)r * 1024 + (c + 1) * 128 + c4 * 4));
                    }
                }
                // MMA on chunk c: warp handles k-slice [w*16, w*16+16)
                float* sH = &arena[(c & 1) * (64 * SHP)];
#pragma unroll
                for (int kk = 0; kk < 2; kk++) {
                    int klocal = warp * 16 + kk * 8;         // within chunk
                    int kglob  = c * 128 + klocal;
                    wmma::fragment<wmma::matrix_a, 16, 16, 8, wmma::precision::tf32, wmma::row_major> af[4];
                    wmma::fragment<wmma::matrix_b, 16, 16, 8, wmma::precision::tf32, wmma::row_major> bfr[2];
#pragma unroll
                    for (int j = 0; j < 2; j++) {
                        wmma::load_matrix_sync(bfr[j], &sW[kglob * SWP + j * 16], SWP);
#pragma unroll
                        for (int e = 0; e < bfr[j].num_elements; e++)
                            bfr[j].x[e] = wmma::__float_to_tf32(bfr[j].x[e]);
                    }
#pragma unroll
                    for (int i = 0; i < 4; i++) {
                        wmma::load_matrix_sync(af[i], &sH[(i * 16) * SHP + klocal], SHP);
#pragma unroll
                        for (int e = 0; e < af[i].num_elements; e++)
                            af[i].x[e] = wmma::__float_to_tf32(af[i].x[e]);
#pragma unroll
                        for (int j = 0; j < 2; j++)
                            wmma::mma_sync(acc[i][j], af[i], bfr[j], acc[i][j]);
                    }
                }
                __syncthreads();
                if (c < 7) {
                    float* sHn = &arena[((c + 1) & 1) * (64 * SHP)];
#pragma unroll
                    for (int l = 0; l < 8; l++) {
                        int idx = tid + l * THREADS;
                        int r = idx >> 5, c4 = idx & 31;
                        float* d = &sHn[r * SHP + c4 * 4];
                        d[0] = pf[l].x; d[1] = pf[l].y; d[2] = pf[l].z; d[3] = pf[l].w;
                    }
                    __syncthreads();
                }
            }

            // store per-warp partials (arena reused; all MMAs done)
            float* sP = arena;   // [8][64][SPP]
#pragma unroll
            for (int i = 0; i < 4; i++)
#pragma unroll
                for (int j = 0; j < 2; j++)
                    wmma::store_matrix_sync(&sP[warp * (64 * SPP) + (i * 16) * SPP + j * 16],
                                            acc[i][j], SPP, wmma::mem_row_major);
            __syncthreads();
        }

        // ---------------- elementwise: gates, state, cummax, outputs ----------
        const float* sP = arena;
        float* __restrict__ hnew = g_hbuf[t & 1];
#pragma unroll
        for (int l = 0; l < 2; l++) {
            int e  = tid + l * THREADS;      // 0..511
            int b  = e >> 3, hh = e & 7;
            int h  = h0 + hh;
            size_t gb = (size_t)(t * 64 + b) * G4;

            float s0 = 0.f, s1 = 0.f, s2 = 0.f, s3 = 0.f;
            if (t > 0) {
#pragma unroll
                for (int w = 0; w < 8; w++) {
                    const float* p = &sP[w * (64 * SPP) + b * SPP];
                    s0 += p[hh];
                    s1 += p[8 + hh];
                    s2 += p[16 + hh];
                    s3 += p[24 + hh];
                }
            }
            float gf = s0 + __ldcg(&g_Gx[gb + h])        + sBias[hh];
            float gi = s1 + __ldcg(&g_Gx[gb + 1024 + h]) + sBias[8 + hh];
            float gc = s2 + __ldcg(&g_Gx[gb + 2048 + h]) + sBias[16 + hh];
            float go = s3 + __ldcg(&g_Gx[gb + 3072 + h]) + sBias[24 + hh];

            float Cn = sigf(gf) * creg[l] + sigf(gi) * tanhf(gc);
            creg[l] = Cn;
            float hv = sigf(go) * tanhf(Cn);

            out[(size_t)b * SEQ * HID + (size_t)t * HID + h] = hv;

            float hm = (t == 0) ? hv : fmaxf(hreg[l], hv);
            hreg[l] = hm;
            hnew[b * HID + h] = hm;

            if (t == SEQ - 1) {
                out[(size_t)BSH + b * HID + h] = hm;                     // h_fin
                out[(size_t)BSH + BATCH * HID + b * HID + h] = Cn;       // C_fin
            }
        }

        // ---------------- grid barrier (release h writes / acquire for t+1) --
        if (t < SEQ - 1) {
            __threadfence();
            __syncthreads();
            if (tid == 0) {
                atomicAdd(&g_bar[t], 1u);
                volatile unsigned* p = &g_bar[t];
                while (*p < (unsigned)CTAS) __nanosleep(64);
            }
            __syncthreads();
        }
    }
}

extern "C" void kernel_launch(void* const* d_in, const int* in_sizes, int n_in,
                              void* d_out, int out_size) {
    const float* x  = (const float*)d_in[0];
    const float* Wf = (const float*)d_in[1];
    const float* bf = (const float*)d_in[2];
    const float* Wi = (const float*)d_in[3];
    const float* bi = (const float*)d_in[4];
    const float* Wc = (const float*)d_in[5];
    const float* bc = (const float*)d_in[6];
    const float* Wo = (const float*)d_in[7];
    const float* bo = (const float*)d_in[8];
    float* out = (float*)d_out;

    static const size_t SMEM = (1024 * SWP + 8 * 64 * SPP) * sizeof(float); // 208896 B
    cudaFuncSetAttribute(k_lstm, cudaFuncAttributeMaxDynamicSharedMemorySize, (int)SMEM);

    k_init<<<1, 512>>>();
    k_gemm_x<<<dim3(32, 256), 256>>>(x, Wf, Wi, Wc, Wo);
    k_lstm<<<CTAS, THREADS, SMEM>>>(Wf, Wi, Wc, Wo, bf, bi, bc, bo, out);
}